// round 7
// baseline (speedup 1.0000x reference)
#include <cuda_runtime.h>

// Ball query (radius=2, nsample=32) + gather(xyz/2, feat) + concat.
// One WARP per query (8 queries / 256-thread block -> 320 blocks = 1 wave).
// Warp scans 128 pts/iteration over [0,1280) with warp-private compaction
// (no block barriers). The ~1% of queries not satisfied there are rescued by
// the whole block: one 60-pt/thread masked pass over [1280,N).
// Gather: warp owns its 32 neighbor rows, shfl-broadcast index, coalesced.

#define KNN 32
#define QPB 8                        // queries (warps) per block
#define THREADS (QPB * 32)
#define GIVEUP 10                    // warp scans GIVEUP*128 = 1280 pts
#define RESCUE_START (GIVEUP * 128)

__device__ __forceinline__ float dist2f(float qq, float qx, float qy, float qz,
                                        float px, float py, float pz) {
    // reference's algebraic form: |q|^2 - 2 q.x + |x|^2
    return qq - 2.0f * (qx * px + qy * py + qz * pz) + (px * px + py * py + pz * pz);
}

// Distance-test 4 consecutive points starting at float4-aligned index b4.
__device__ __forceinline__ unsigned test4(const float* __restrict__ p, int b4,
                                          float qq, float qx, float qy, float qz)
{
    const float4* pv = reinterpret_cast<const float4*>(p + (size_t)b4 * 3);
    const float4 v0 = pv[0], v1 = pv[1], v2 = pv[2];
    const float d0 = dist2f(qq, qx, qy, qz, v0.x, v0.y, v0.z);
    const float d1 = dist2f(qq, qx, qy, qz, v0.w, v1.x, v1.y);
    const float d2 = dist2f(qq, qx, qy, qz, v1.z, v1.w, v2.x);
    const float d3 = dist2f(qq, qx, qy, qz, v2.y, v2.z, v2.w);
    return (d0 <= 4.0f ? 1u : 0u) | (d1 <= 4.0f ? 2u : 0u)
         | (d2 <= 4.0f ? 4u : 0u) | (d3 <= 4.0f ? 8u : 0u);
}

__global__ __launch_bounds__(THREADS)
void ball_query_gather_kernel(
    const float* __restrict__ q_xyz,   // (Q, 3)
    const float* __restrict__ pts,     // (B, N, 3)
    const float* __restrict__ feat,    // (B, N, 32)
    float* __restrict__ out,           // (Q, KNN, 35)
    int Q, int N, int Qper)
{
    const int tid  = threadIdx.x;
    const int warp = tid >> 5;
    const int lane = tid & 31;
    const int q    = blockIdx.x * QPB + warp;

    __shared__ int      s_idx[QPB][KNN];
    __shared__ int      s_cnt[QPB];
    __shared__ float    s_q[QPB][4];
    __shared__ unsigned s_w[2][QPB];

    const int bq = (q < Q) ? q : 0;
    const int b  = bq / Qper;
    const float* __restrict__ p = pts  + (size_t)b * N * 3;
    const float* __restrict__ f = feat + (size_t)b * N * 32;

    float qx = 0.f, qy = 0.f, qz = 0.f, qq = 0.f;
    int count = KNN;                       // invalid warps act "done"
    if (q < Q) {
        qx = q_xyz[q * 3 + 0];
        qy = q_xyz[q * 3 + 1];
        qz = q_xyz[q * 3 + 2];
        qq = qx * qx + qy * qy + qz * qz;
        count = 0;

        // --- warp-autonomous scan: 128 pts / iteration, no block barriers ---
        for (int it = 0; it < GIVEUP && count < KNN; ++it) {
            const int base = it * 128 + 4 * lane;
            unsigned bits = test4(p, base, qq, qx, qy, qz);
            const int c = __popc(bits);
            int inc = c;
            #pragma unroll
            for (int off = 1; off < 32; off <<= 1) {
                const int v = __shfl_up_sync(0xffffffffu, inc, off);
                if (lane >= off) inc += v;
            }
            int slot = count + inc - c;
            while (bits && slot < KNN) {
                const int j = __ffs(bits) - 1;
                bits &= bits - 1u;
                s_idx[warp][slot++] = base + j;
            }
            count += __shfl_sync(0xffffffffu, inc, 31);
        }
    }
    if (lane == 0) {
        s_cnt[warp] = count;
        s_q[warp][0] = qx; s_q[warp][1] = qy;
        s_q[warp][2] = qz; s_q[warp][3] = qq;
    }
    __syncthreads();

    // --- block rescue of warps that gave up (rare: ~1% of queries) ---
    int buf = 0;
    for (int w = 0; w < QPB; ++w) {
        if (s_cnt[w] >= KNN) continue;             // uniform branch (smem)
        const float rqx = s_q[w][0], rqy = s_q[w][1];
        const float rqz = s_q[w][2], rqq = s_q[w][3];
        int wcount = s_cnt[w];
        for (int s0 = RESCUE_START; s0 < N && wcount < KNN; s0 += 60 * THREADS) {
            const int tstart = s0 + 60 * tid;
            unsigned long long mask = 0ull;
            #pragma unroll 3
            for (int i = 0; i < 15; ++i) {
                const int b4 = tstart + 4 * i;
                if (b4 + 4 <= N) {
                    mask |= (unsigned long long)test4(p, b4, rqq, rqx, rqy, rqz)
                            << (4 * i);
                } else {
                    for (int j = 0; j < 4; ++j) {
                        const int n = b4 + j;
                        if (n < N) {
                            const float d = dist2f(rqq, rqx, rqy, rqz,
                                                   p[n*3+0], p[n*3+1], p[n*3+2]);
                            if (d <= 4.0f) mask |= 1ull << (4 * i + j);
                        }
                    }
                }
            }
            const int c = __popcll(mask);
            int inc = c;
            #pragma unroll
            for (int off = 1; off < 32; off <<= 1) {
                const int v = __shfl_up_sync(0xffffffffu, inc, off);
                if (lane >= off) inc += v;
            }
            if (lane == 31) s_w[buf][warp] = (unsigned)inc;
            __syncthreads();
            int wbase = 0, total = 0;
            #pragma unroll
            for (int ww = 0; ww < QPB; ++ww) {
                const int t = (int)s_w[buf][ww];
                if (ww < warp) wbase += t;
                total += t;
            }
            int slot = wcount + wbase + (inc - c);
            unsigned long long bits = mask;
            while (bits && slot < KNN) {
                const int j = __ffsll(bits) - 1;
                bits &= bits - 1ull;
                s_idx[w][slot++] = tstart + j;
            }
            wcount += total;
            buf ^= 1;                      // parity-buffer s_w, no extra barrier
        }
        if (tid == 0) s_cnt[w] = wcount;
        __syncthreads();                   // publish s_idx[w] / s_cnt[w]
    }

    // --- fill + gather (warp-owned) ---
    if (q < Q) {
        __syncwarp();
        const int cnt = s_cnt[warp];
        if (cnt < KNN) {                   // degenerate fill (rare)
            const int first = (cnt > 0) ? s_idx[warp][0] : (N - 1); // JAX clamp
            if (lane >= cnt) s_idx[warp][lane] = first;
            __syncwarp();
        }
        const int myidx = s_idx[warp][lane];   // lane k holds neighbor k
        float* __restrict__ o = out + (size_t)q * KNN * 35;
        #pragma unroll 4
        for (int k = 0; k < KNN; ++k) {
            const int idx = __shfl_sync(0xffffffffu, myidx, k);
            o[k * 35 + 3 + lane] = f[idx * 32 + lane];       // 128B coalesced
            if (lane < 3)
                o[k * 35 + lane] = p[idx * 3 + lane] * 0.5f; // nn_xyz / D_RADIUS
        }
    }
}

extern "C" void kernel_launch(void* const* d_in, const int* in_sizes, int n_in,
                              void* d_out, int out_size) {
    const float* candidate_pts = (const float*)d_in[0];  // (B,128,10,3)
    const float* tgt_pts_xyz   = (const float*)d_in[2];  // (B,N,3)
    const float* tgt_feat      = (const float*)d_in[3];  // (B,N,32)
    float* out = (float*)d_out;

    const int B = 2;
    const int Q = in_sizes[0] / 3;           // 2560
    const int N = in_sizes[2] / (3 * B);     // 16384
    const int Qper = Q / B;                  // 1280

    const int blocks = (Q + QPB - 1) / QPB;  // 320
    ball_query_gather_kernel<<<blocks, THREADS>>>(
        candidate_pts, tgt_pts_xyz, tgt_feat, out, Q, N, Qper);
}

// round 8
// speedup vs baseline: 1.2600x; 1.2600x over previous
#include <cuda_runtime.h>

// Ball query (radius=2, nsample=32) + gather(xyz/2, feat) + concat.
// One 128-thread block per query (16 blocks/SM resident -> ~whole grid in one
// wave). Geometric 4-phase adaptive scan, 4 pts/thread float4 from phase 0:
//   phase 0: [0,512)        4 pts/thread   (~98.5% of queries stop here)
//   phase 1: [512,2560)    16 pts/thread
//   phase 2: [2560,10752)  64 pts/thread
//   phase 3: [10752,N)     44 pts/thread   (vanishingly rare)
// Ordered block compaction per phase: warp shfl scan + parity-buffered
// per-warp totals (one barrier per phase).

#define KNN 32
#define THREADS 128
#define NWARP (THREADS / 32)   // 4

__device__ __forceinline__ float dist2f(float qq, float qx, float qy, float qz,
                                        float px, float py, float pz) {
    // reference's algebraic form: |q|^2 - 2 q.x + |x|^2
    return qq - 2.0f * (qx * px + qy * py + qz * pz) + (px * px + py * py + pz * pz);
}

// Distance-test 4 consecutive points starting at float4-aligned index b4.
__device__ __forceinline__ unsigned test4(const float* __restrict__ p, int b4,
                                          float qq, float qx, float qy, float qz)
{
    const float4* pv = reinterpret_cast<const float4*>(p + (size_t)b4 * 3);
    const float4 v0 = pv[0], v1 = pv[1], v2 = pv[2];
    const float d0 = dist2f(qq, qx, qy, qz, v0.x, v0.y, v0.z);
    const float d1 = dist2f(qq, qx, qy, qz, v0.w, v1.x, v1.y);
    const float d2 = dist2f(qq, qx, qy, qz, v1.z, v1.w, v2.x);
    const float d3 = dist2f(qq, qx, qy, qz, v2.y, v2.z, v2.w);
    return (d0 <= 4.0f ? 1u : 0u) | (d1 <= 4.0f ? 2u : 0u)
         | (d2 <= 4.0f ? 4u : 0u) | (d3 <= 4.0f ? 8u : 0u);
}

// Ordered compaction of this phase's hits into s_idx. Bit j of ok_bits set
// means point (base_ptidx + j) is in radius. Returns updated block count.
__device__ __forceinline__ int compact_write(
    unsigned long long ok_bits, int base_ptidx,
    int warp, int lane, int buf,
    volatile unsigned s_wcnt[2][NWARP], int* s_idx, int count)
{
    const int c = __popcll(ok_bits);
    int inc = c;
    #pragma unroll
    for (int off = 1; off < 32; off <<= 1) {
        const int v = __shfl_up_sync(0xffffffffu, inc, off);
        if (lane >= off) inc += v;
    }
    if (lane == 31) s_wcnt[buf][warp] = (unsigned)inc;
    __syncthreads();                               // only barrier per phase

    int wbase = 0, total = 0;
    #pragma unroll
    for (int w = 0; w < NWARP; ++w) {
        const int t = (int)s_wcnt[buf][w];
        if (w < warp) wbase += t;
        total += t;
    }
    int slot = count + wbase + (inc - c);
    unsigned long long bits = ok_bits;
    while (bits && slot < KNN) {
        const int j = __ffsll(bits) - 1;
        bits &= bits - 1ull;
        s_idx[slot++] = base_ptidx + j;
    }
    return count + total;
}

__global__ __launch_bounds__(THREADS)
void ball_query_gather_kernel(
    const float* __restrict__ q_xyz,   // (Q, 3)
    const float* __restrict__ pts,     // (B, N, 3)
    const float* __restrict__ feat,    // (B, N, 32)
    float* __restrict__ out,           // (Q, KNN, 35)
    int Q, int N, int Qper)
{
    const int q    = blockIdx.x;
    const int tid  = threadIdx.x;
    const int warp = tid >> 5;
    const int lane = tid & 31;

    __shared__ int      s_idx[KNN];
    __shared__ unsigned s_wcnt[2][NWARP];

    const int b = q / Qper;
    const float* __restrict__ p = pts  + (size_t)b * N * 3;
    const float* __restrict__ f = feat + (size_t)b * N * 32;

    const float qx = q_xyz[q * 3 + 0];
    const float qy = q_xyz[q * 3 + 1];
    const float qz = q_xyz[q * 3 + 2];
    const float qq = qx * qx + qy * qy + qz * qz;

    // --- phase 0: [0,512), 4 points per thread (float4) ---
    int count;
    {
        const int b4 = 4 * tid;
        unsigned bits = 0;
        if (b4 + 4 <= N) bits = test4(p, b4, qq, qx, qy, qz);
        count = compact_write(bits, b4, warp, lane, 0, s_wcnt, s_idx, 0);
    }

    // --- phase 1: [512,2560), 16 points per thread ---
    if (count < KNN) {
        const int tstart = 4 * THREADS + 16 * tid;
        unsigned long long mask = 0ull;
        #pragma unroll
        for (int i = 0; i < 4; ++i) {
            const int b4 = tstart + 4 * i;
            if (b4 + 4 <= N)
                mask |= (unsigned long long)test4(p, b4, qq, qx, qy, qz) << (4 * i);
        }
        count = compact_write(mask, tstart, warp, lane, 1, s_wcnt, s_idx, count);
    }

    // --- phase 2: [2560,10752), 64 points per thread ---
    if (count < KNN) {
        const int tstart = 20 * THREADS + 64 * tid;
        unsigned long long mask = 0ull;
        #pragma unroll 2
        for (int i = 0; i < 16; ++i) {
            const int b4 = tstart + 4 * i;
            if (b4 + 4 <= N)
                mask |= (unsigned long long)test4(p, b4, qq, qx, qy, qz) << (4 * i);
        }
        count = compact_write(mask, tstart, warp, lane, 0, s_wcnt, s_idx, count);
    }

    // --- phase 3: [10752,N), 44 points per thread (vanishingly rare) ---
    if (count < KNN) {
        const int tstart = 84 * THREADS + 44 * tid;
        unsigned long long mask = 0ull;
        #pragma unroll 2
        for (int i = 0; i < 11; ++i) {
            const int b4 = tstart + 4 * i;
            if (b4 + 4 <= N) {
                mask |= (unsigned long long)test4(p, b4, qq, qx, qy, qz) << (4 * i);
            } else {
                for (int j = 0; j < 4; ++j) {
                    const int n = b4 + j;
                    if (n < N) {
                        const float d = dist2f(qq, qx, qy, qz,
                                               p[n*3+0], p[n*3+1], p[n*3+2]);
                        if (d <= 4.0f) mask |= 1ull << (4 * i + j);
                    }
                }
            }
        }
        count = compact_write(mask, tstart, warp, lane, 1, s_wcnt, s_idx, count);
    }
    __syncthreads();   // publish s_idx

    // --- degenerate fill ---
    if (count < KNN) {
        const int first = (count > 0) ? s_idx[0] : (N - 1);  // JAX clamps OOB gather
        if (tid >= count && tid < KNN) s_idx[tid] = first;
        __syncthreads();
    }

    // --- gather + concat: 4 warps x 8 independent neighbor rows, coalesced ---
    float* __restrict__ o = out + (size_t)q * KNN * 35;
    int kidx[KNN / NWARP];
    #pragma unroll
    for (int i = 0; i < KNN / NWARP; ++i)
        kidx[i] = s_idx[warp * (KNN / NWARP) + i];
    #pragma unroll
    for (int i = 0; i < KNN / NWARP; ++i) {
        const int k   = warp * (KNN / NWARP) + i;
        const int idx = kidx[i];
        o[k * 35 + 3 + lane] = f[idx * 32 + lane];        // 128B coalesced
        if (lane < 3)
            o[k * 35 + lane] = p[idx * 3 + lane] * 0.5f;  // nn_xyz / D_RADIUS
    }
}

extern "C" void kernel_launch(void* const* d_in, const int* in_sizes, int n_in,
                              void* d_out, int out_size) {
    const float* candidate_pts = (const float*)d_in[0];  // (B,128,10,3)
    const float* tgt_pts_xyz   = (const float*)d_in[2];  // (B,N,3)
    const float* tgt_feat      = (const float*)d_in[3];  // (B,N,32)
    float* out = (float*)d_out;

    const int B = 2;
    const int Q = in_sizes[0] / 3;           // 2560
    const int N = in_sizes[2] / (3 * B);     // 16384
    const int Qper = Q / B;                  // 1280

    ball_query_gather_kernel<<<Q, THREADS>>>(
        candidate_pts, tgt_pts_xyz, tgt_feat, out, Q, N, Qper);
}